// round 16
// baseline (speedup 1.0000x reference)
#include <cuda_runtime.h>
#include <cuda_fp16.h>
#include <cstdint>

#define HIDDEN 1024
#define HEADS 16
#define HD 64
#define NVID 2048
#define NACT 16
#define NTOT 2064
#define BSZ 2
#define BH (BSZ*HEADS)
// q pre-scale: ATT_SCALE * log2(e), so softmax uses exp2
#define QSC 0.18033688011112042f

#define WSZ 1048576LL
#define OFF_VIDEO 0LL
#define OFF_ACTION 4194304LL
#define OFF_W 4227072LL
#define OFF_CTX (OFF_W + 8LL * WSZ)
#define BF_TOTAL (OFF_CTX + 4227072LL)

// ---------------- scratch (device globals; no allocation allowed) ----------------
__device__ unsigned short g_bh[BF_TOTAL];    // fp16: inputs, weights, ctx
__device__ unsigned short g_qh[BH * NTOT * HD];
__device__ unsigned short g_kh[BH * NTOT * HD];
__device__ unsigned short g_vh[BH * NTOT * HD];

// ---------------- helpers ----------------
__device__ __forceinline__ void cpa16z(uint32_t dst, const void* src, int bytes) {
    asm volatile("cp.async.cg.shared.global [%0], [%1], 16, %2;"
                 :: "r"(dst), "l"(src), "r"(bytes) : "memory");
}
__device__ __forceinline__ void cp_commit() {
    asm volatile("cp.async.commit_group;" ::: "memory");
}
__device__ __forceinline__ uint32_t smem_u32(const void* p) {
    return (uint32_t)__cvta_generic_to_shared(p);
}
__device__ __forceinline__ void ldm4(uint32_t* r, uint32_t addr) {
    asm volatile("ldmatrix.sync.aligned.m8n8.x4.shared.b16 {%0,%1,%2,%3}, [%4];"
                 : "=r"(r[0]), "=r"(r[1]), "=r"(r[2]), "=r"(r[3]) : "r"(addr));
}
__device__ __forceinline__ void ldm4t(uint32_t* r, uint32_t addr) {
    asm volatile("ldmatrix.sync.aligned.m8n8.x4.trans.shared.b16 {%0,%1,%2,%3}, [%4];"
                 : "=r"(r[0]), "=r"(r[1]), "=r"(r[2]), "=r"(r[3]) : "r"(addr));
}
__device__ __forceinline__ void mma16816(float* c, const uint32_t* a,
                                         uint32_t b0, uint32_t b1) {
    asm volatile("mma.sync.aligned.m16n8k16.row.col.f32.f16.f16.f32 "
                 "{%0,%1,%2,%3}, {%4,%5,%6,%7}, {%8,%9}, {%0,%1,%2,%3};"
                 : "+f"(c[0]), "+f"(c[1]), "+f"(c[2]), "+f"(c[3])
                 : "r"(a[0]), "r"(a[1]), "r"(a[2]), "r"(a[3]), "r"(b0), "r"(b1));
}
__device__ __forceinline__ unsigned short h16(float x) {
    return __half_as_ushort(__float2half_rn(x));
}
__device__ __forceinline__ uint32_t pkh(float lo, float hi) {
    uint32_t r;
    asm("cvt.rn.f16x2.f32 %0, %1, %2;" : "=r"(r) : "f"(hi), "f"(lo));
    return r;
}
__device__ __forceinline__ float ex2f(float x) {
    float y; asm("ex2.approx.ftz.f32 %0, %1;" : "=f"(y) : "f"(x)); return y;
}

// ---------------- fp32 -> fp16 convert (inputs + weights), 16B stores ----------------
__global__ void cvt_all(const float* v, const float* a,
                        const float* w0, const float* w1, const float* w2,
                        const float* w3, const float* w4, const float* w5,
                        const float* w6, const float* w7)
{
    const float* srcs[10] = { v, a, w0, w1, w2, w3, w4, w5, w6, w7 };
    const long long offs[10] = { OFF_VIDEO, OFF_ACTION,
        OFF_W + 0 * WSZ, OFF_W + 1 * WSZ, OFF_W + 2 * WSZ, OFF_W + 3 * WSZ,
        OFF_W + 4 * WSZ, OFF_W + 5 * WSZ, OFF_W + 6 * WSZ, OFF_W + 7 * WSZ };
    const int cnts[10] = { 4194304, 32768, 1048576, 1048576, 1048576, 1048576,
                           1048576, 1048576, 1048576, 1048576 };
    const int z = blockIdx.y;
    const float4* src = (const float4*)srcs[z];
    uint4* dst = (uint4*)(g_bh + offs[z]);
    const int n8 = cnts[z] >> 3;
    for (int i = blockIdx.x * blockDim.x + threadIdx.x; i < n8;
         i += gridDim.x * blockDim.x) {
        const float4 x = src[2 * i];
        const float4 y = src[2 * i + 1];
        uint4 o;
        o.x = pkh(x.x, x.y);
        o.y = pkh(x.z, x.w);
        o.z = pkh(y.x, y.y);
        o.w = pkh(y.z, y.w);
        dst[i] = o;
    }
}

// ================= qkv GEMM: 128x128 tile, 512 threads (at HMMA ceiling) =========
#define GT_TILE 16384
#define GT_BUF  (2 * GT_TILE)
#define GT_SMEM (2 * GT_BUF)          // 64 KB

__device__ __forceinline__ void gstage(const unsigned short* Ah,
                                       int M, int rowTile,
                                       const unsigned short* Wh,
                                       int colTile, int k0, uint32_t bufb, int tid)
{
#pragma unroll
    for (int i = 0; i < 4; i++) {
        const int tile = i >> 1;
        const int t = ((i & 1) << 9) + tid;
        const int row = t >> 3, c = t & 7;
        const uint32_t dst = bufb + tile * GT_TILE + (row << 7) + ((c ^ (row & 7)) << 4);
        if (tile == 0) {
            const int m = rowTile + row;
            const int mm = (m < M) ? m : 0;
            cpa16z(dst, Ah + (long long)mm * 1024 + k0 + c * 8, (m < M) ? 16 : 0);
        } else {
            cpa16z(dst, Wh + (long long)(colTile + row) * 1024 + k0 + c * 8, 16);
        }
    }
}

// MODE 1: video qkv + rope;  MODE 2: action qkv
template <int MODE>
__device__ __forceinline__ void gemm_body(const unsigned short* Ah,
                                          int M, int rowTile,
                                          const unsigned short* Wh,
                                          int colTile, const float* bias,
                                          unsigned short* __restrict__ oh, int rk)
{
    extern __shared__ char dsmem[];
    const uint32_t sbase = smem_u32(dsmem);
    const int tid = threadIdx.x;
    const int lane = tid & 31, wid = tid >> 5;
    const int warp_m = wid >> 2, warp_n = wid & 3;

    float acc[2][4][4];
#pragma unroll
    for (int a = 0; a < 2; a++)
#pragma unroll
        for (int b = 0; b < 4; b++)
#pragma unroll
            for (int c = 0; c < 4; c++) acc[a][b][c] = 0.f;

    int rA[2], rW[2];
#pragma unroll
    for (int mt = 0; mt < 2; mt++) rA[mt] = warp_m * 32 + mt * 16 + (lane & 15);
#pragma unroll
    for (int nt2 = 0; nt2 < 2; nt2++) rW[nt2] = warp_n * 32 + nt2 * 16 + (lane & 15);
    const int khalf = lane >> 4;

    gstage(Ah, M, rowTile, Wh, colTile, 0, sbase, tid);
    cp_commit();

    for (int c = 0; c < 16; c++) {
        if (c + 1 < 16) {
            gstage(Ah, M, rowTile, Wh, colTile, (c + 1) * 64,
                   sbase + ((c + 1) & 1) * GT_BUF, tid);
            cp_commit();
            asm volatile("cp.async.wait_group 1;" ::: "memory");
        } else {
            asm volatile("cp.async.wait_group 0;" ::: "memory");
        }
        __syncthreads();

        const uint32_t bufb = sbase + (c & 1) * GT_BUF;
        const uint32_t sAh = bufb;
        const uint32_t sWh = bufb + GT_TILE;

#pragma unroll
        for (int kq = 0; kq < 4; kq++) {
            const int kp = 2 * kq + khalf;
            uint32_t ah[2][4], wh[2][4];
#pragma unroll
            for (int mt = 0; mt < 2; mt++) {
                const uint32_t off = (rA[mt] << 7) + ((kp ^ (rA[mt] & 7)) << 4);
                ldm4(ah[mt], sAh + off);
            }
#pragma unroll
            for (int nt2 = 0; nt2 < 2; nt2++) {
                const uint32_t off = (rW[nt2] << 7) + ((kp ^ (rW[nt2] & 7)) << 4);
                ldm4(wh[nt2], sWh + off);
            }
#pragma unroll
            for (int mt = 0; mt < 2; mt++) {
#pragma unroll
                for (int nt = 0; nt < 4; nt++) {
                    const uint32_t* whf = wh[nt >> 1];
                    mma16816(acc[mt][nt], ah[mt], whf[nt & 1], whf[(nt & 1) + 2]);
                }
            }
        }
        __syncthreads();
    }

    const int g = lane >> 2, tg = lane & 3;
#pragma unroll
    for (int mt = 0; mt < 2; mt++) {
#pragma unroll
        for (int nt = 0; nt < 4; nt++) {
            const int n0 = colTile + warp_n * 32 + nt * 8 + tg * 2;
            const float2 bv = *(const float2*)(bias + n0);
#pragma unroll
            for (int hf = 0; hf < 2; hf++) {
                const int m = rowTile + warp_m * 32 + mt * 16 + g + hf * 8;
                if (m >= M) continue;
                float v0 = acc[mt][nt][hf * 2 + 0] + bv.x;
                float v1 = acc[mt][nt][hf * 2 + 1] + bv.y;
                int b_, nn;
                if (MODE == 1) { b_ = m >> 11; nn = m & 2047; }
                else           { b_ = m >> 4;  nn = NVID + (m & 15); }
                const int hh = n0 >> 6, d = n0 & 63;
                if (MODE == 1 && rk && d < 60) {
                    const int seg = d / 20, jj = (d - seg * 20) >> 1;
                    const int pos = (seg == 0) ? (nn >> 8)
                                  : (seg == 1) ? ((nn >> 4) & 15) : (nn & 15);
                    const float omega = ex2f(-(float)jj * 1.3287712379549449f);
                    float sn, cs;
                    sincosf((float)pos * omega, &sn, &cs);
                    const float x1 = v0 * cs - v1 * sn;
                    const float x2 = v1 * cs + v0 * sn;
                    v0 = x1; v1 = x2;
                }
                if (rk == 1) { v0 *= QSC; v1 *= QSC; }
                const long long idx = (((long long)(b_ * HEADS + hh)) * NTOT + nn) * HD + d;
                *(ushort2*)(oh + idx) = make_ushort2(h16(v0), h16(v1));
            }
        }
    }
}

// grid (8, 33, 3): z = {q,k,v}; by<32 video rows; by==32 action rows
__global__ __launch_bounds__(512, 1)
void gemm_qkv_mma(const float* bq, const float* bk, const float* bv,
                  const float* bqa, const float* bka, const float* bva)
{
    const int z = blockIdx.z;
    const bool act = (blockIdx.y == 32);
    const unsigned short* Ah = g_bh + (act ? OFF_ACTION : OFF_VIDEO);
    const int M = act ? (BSZ * NACT) : (BSZ * NVID);
    const int rowTile = act ? 0 : blockIdx.y * 128;
    const int colTile = blockIdx.x * 128;
    const int widx = z + (act ? 3 : 0);
    const unsigned short* Wh = g_bh + OFF_W + widx * WSZ;
    const float* bias = act ? (z == 0 ? bqa : (z == 1 ? bka : bva))
                            : (z == 0 ? bq : (z == 1 ? bk : bv));
    unsigned short* oh;
    int rk;
    if (z == 0)      { oh = g_qh; rk = 1; }
    else if (z == 1) { oh = g_kh; rk = 2; }
    else             { oh = g_vh; rk = 0; }
    if (act) gemm_body<2>(Ah, M, rowTile, Wh, colTile, bias, oh, rk);
    else     gemm_body<1>(Ah, M, rowTile, Wh, colTile, bias, oh, rk);
}

// ================= out GEMM: 128x64 tile, 256 threads, 2 CTAs/SM =================
#define GO_ATILE 16384                 // 128 rows * 128 B
#define GO_WTILE 8192                  // 64 rows * 128 B
#define GO_BUF   (GO_ATILE + GO_WTILE) // 24 KB
#define GO_SMEM  (2 * GO_BUF)          // 48 KB

__device__ __forceinline__ void gstage_o(const unsigned short* Ah,
                                         int M, int rowTile,
                                         const unsigned short* Wh,
                                         int colTile, int k0, uint32_t bufb, int tid)
{
#pragma unroll
    for (int i = 0; i < 6; i++) {
        if (i < 4) {       // A tile: 1024 chunks
            const int t = (i << 8) + tid;
            const int row = t >> 3, c = t & 7;
            const uint32_t dst = bufb + (row << 7) + ((c ^ (row & 7)) << 4);
            const int m = rowTile + row;
            const int mm = (m < M) ? m : 0;
            cpa16z(dst, Ah + (long long)mm * 1024 + k0 + c * 8, (m < M) ? 16 : 0);
        } else {           // W tile: 512 chunks
            const int t = ((i - 4) << 8) + tid;
            const int row = t >> 3, c = t & 7;
            const uint32_t dst = bufb + GO_ATILE + (row << 7) + ((c ^ (row & 7)) << 4);
            cpa16z(dst, Wh + (long long)(colTile + row) * 1024 + k0 + c * 8, 16);
        }
    }
}

// grid (16, 17, 2): z = batch; by<16 video rows; by==16 action rows
__global__ __launch_bounds__(256, 2)
void gemm_out_mma(const float* bp, const float* bpa, float* __restrict__ dout)
{
    extern __shared__ char dsmem[];
    const uint32_t sbase = smem_u32(dsmem);
    const int z = blockIdx.z;
    const bool act = (blockIdx.y == 16);
    const long long aoff = OFF_CTX + (long long)z * NTOT * HIDDEN +
                           (act ? (long long)NVID * HIDDEN : 0);
    const unsigned short* Ah = g_bh + aoff;
    const int M = act ? NACT : NVID;
    const int rowTile = act ? 0 : blockIdx.y * 128;
    const int colTile = blockIdx.x * 64;
    const int widx = act ? 7 : 6;
    const unsigned short* Wh = g_bh + OFF_W + widx * WSZ;
    const float* bias = act ? bpa : bp;
    float* C = act ? (dout + (long long)BSZ * NVID * HIDDEN + (long long)z * NACT * HIDDEN)
                   : (dout + (long long)z * NVID * HIDDEN);

    const int tid = threadIdx.x;
    const int lane = tid & 31, wid = tid >> 5;
    const int warp_m = wid >> 1, warp_n = wid & 1;   // 4 x 2 warps

    float acc[2][4][4];
#pragma unroll
    for (int a = 0; a < 2; a++)
#pragma unroll
        for (int b = 0; b < 4; b++)
#pragma unroll
            for (int c = 0; c < 4; c++) acc[a][b][c] = 0.f;

    int rA[2], rW[2];
#pragma unroll
    for (int mt = 0; mt < 2; mt++) rA[mt] = warp_m * 32 + mt * 16 + (lane & 15);
#pragma unroll
    for (int nt2 = 0; nt2 < 2; nt2++) rW[nt2] = warp_n * 32 + nt2 * 16 + (lane & 15);
    const int khalf = lane >> 4;

    gstage_o(Ah, M, rowTile, Wh, colTile, 0, sbase, tid);
    cp_commit();

    for (int c = 0; c < 16; c++) {
        if (c + 1 < 16) {
            gstage_o(Ah, M, rowTile, Wh, colTile, (c + 1) * 64,
                     sbase + ((c + 1) & 1) * GO_BUF, tid);
            cp_commit();
            asm volatile("cp.async.wait_group 1;" ::: "memory");
        } else {
            asm volatile("cp.async.wait_group 0;" ::: "memory");
        }
        __syncthreads();

        const uint32_t bufb = sbase + (c & 1) * GO_BUF;
        const uint32_t sAh = bufb;
        const uint32_t sWh = bufb + GO_ATILE;

#pragma unroll
        for (int kq = 0; kq < 4; kq++) {
            const int kp = 2 * kq + khalf;
            uint32_t ah[2][4], wh[2][4];
#pragma unroll
            for (int mt = 0; mt < 2; mt++) {
                const uint32_t off = (rA[mt] << 7) + ((kp ^ (rA[mt] & 7)) << 4);
                ldm4(ah[mt], sAh + off);
            }
#pragma unroll
            for (int nt2 = 0; nt2 < 2; nt2++) {
                const uint32_t off = (rW[nt2] << 7) + ((kp ^ (rW[nt2] & 7)) << 4);
                ldm4(wh[nt2], sWh + off);
            }
#pragma unroll
            for (int mt = 0; mt < 2; mt++) {
#pragma unroll
                for (int nt = 0; nt < 4; nt++) {
                    const uint32_t* whf = wh[nt >> 1];
                    mma16816(acc[mt][nt], ah[mt], whf[nt & 1], whf[(nt & 1) + 2]);
                }
            }
        }
        __syncthreads();
    }

    const int g = lane >> 2, tg = lane & 3;
#pragma unroll
    for (int mt = 0; mt < 2; mt++) {
#pragma unroll
        for (int nt = 0; nt < 4; nt++) {
            const int n0 = colTile + warp_n * 32 + nt * 8 + tg * 2;
            const float2 bv = *(const float2*)(bias + n0);
#pragma unroll
            for (int hf = 0; hf < 2; hf++) {
                const int m = rowTile + warp_m * 32 + mt * 16 + g + hf * 8;
                if (m >= M) continue;
                float2 o;
                o.x = acc[mt][nt][hf * 2 + 0] + bv.x;
                o.y = acc[mt][nt][hf * 2 + 1] + bv.y;
                *(float2*)(C + (long long)m * 1024 + n0) = o;
            }
        }
    }
}

// ================= flash attention: 128 q-rows, 8 warps, 2 CTAs/SM =============
// Triple-buffered fused K+V tiles (16 KB each: K at +0, V at +8K).
// One wait_group(1) + one __syncthreads per key tile; prefetch distance 2.
// KV global traffic halved vs 64-q CTAs (each CTA serves 128 q rows).
#define AT_QOFF 0
#define AT_BUF(i) (16384 + (i) * 16384)
#define AT_SMEM (16384 + 3 * 16384)   // 65536

__device__ __forceinline__ void stage_kv64(long long base, int kt, uint32_t bufb, int tid) {
#pragma unroll
    for (int i = 0; i < 4; i++) {
        const int arr = i >> 1;                  // 0 = K, 1 = V
        const int t = ((i & 1) << 8) + tid;      // 0..511
        const int row = t >> 3, c = t & 7;
        const int key = kt * 64 + row;
        const uint32_t dst = bufb + arr * 8192 + (row << 7) + ((c ^ (row & 7)) << 4);
        const unsigned short* s = (arr == 0 ? g_kh : g_vh) +
            base + (long long)(key < NTOT ? key : 0) * HD + c * 8;
        cpa16z(dst, s, (key < NTOT) ? 16 : 0);
    }
}

__global__ __launch_bounds__(256, 2)
void attn_mma()
{
    extern __shared__ char dsm[];
    const uint32_t sb = smem_u32(dsm);
    const int tid = threadIdx.x, lane = tid & 31, w = tid >> 5;   // 8 warps
    const int qt = blockIdx.x, bh = blockIdx.y;
    const int b = bh >> 4, h = bh & 15;
    const long long base = (long long)bh * NTOT * HD;
    const int g = lane >> 2, tg = lane & 3;
    const int khalf = lane >> 4, l15 = lane & 15;

    // prologue: G0 = {Q(128 rows), KV0}, G1 = {KV1}
#pragma unroll
    for (int i = 0; i < 4; i++) {
        const int t = (i << 8) + tid;            // 0..1023
        const int row = t >> 3, c = t & 7;
        const int n = qt * 128 + row;
        const uint32_t dst = sb + AT_QOFF + (row << 7) + ((c ^ (row & 7)) << 4);
        const unsigned short* src = g_qh + base + (long long)(n < NTOT ? n : 0) * HD + c * 8;
        cpa16z(dst, src, (n < NTOT) ? 16 : 0);
    }
    stage_kv64(base, 0, sb + AT_BUF(0), tid);
    cp_commit();
    stage_kv64(base, 1, sb + AT_BUF(1), tid);
    cp_commit();

    float oacc[8][4];
#pragma unroll
    for (int i = 0; i < 8; i++)
#pragma unroll
        for (int j = 0; j < 4; j++) oacc[i][j] = 0.f;
    float m0 = -1e30f, m1 = -1e30f, l0 = 0.f, l1 = 0.f;
    uint32_t qfh[4][4];

    const int NKT = 33;   // 33 * 64 = 2112 >= 2064
    int bi = 0;           // kt % 3
    for (int kt = 0; kt < NKT; kt++) {
        asm volatile("cp.async.wait_group 1;" ::: "memory");
        __syncthreads();

        if (kt == 0) {   // Q fragments (once): warp w owns rows qt*128 + w*16..+16
            const int row = w * 16 + l15;
#pragma unroll
            for (int kq = 0; kq < 4; kq++) {
                const int kp = 2 * kq + khalf;
                const uint32_t off = (row << 7) + ((kp ^ (row & 7)) << 4);
                ldm4(qfh[kq], sb + AT_QOFF + off);
            }
        }

        // prefetch KV(kt+2) into the buffer consumed at iteration kt-1
        if (kt + 2 < NKT) {
            int nb = bi + 2; if (nb >= 3) nb -= 3;
            stage_kv64(base, kt + 2, sb + AT_BUF(nb), tid);
        }
        cp_commit();

        const uint32_t sKh = sb + AT_BUF(bi);
        const uint32_t sVh = sKh + 8192;

        float sacc[8][4];
#pragma unroll
        for (int i = 0; i < 8; i++)
#pragma unroll
            for (int j = 0; j < 4; j++) sacc[i][j] = 0.f;

        // S = Q*K, 64 keys
#pragma unroll
        for (int kq = 0; kq < 4; kq++) {
            const int kp = 2 * kq + khalf;
#pragma unroll
            for (int ng = 0; ng < 4; ng++) {
                const int row = ng * 16 + l15;
                const uint32_t off = (row << 7) + ((kp ^ (row & 7)) << 4);
                uint32_t kh4[4];
                ldm4(kh4, sKh + off);
                mma16816(sacc[2 * ng + 0], qfh[kq], kh4[0], kh4[2]);
                mma16816(sacc[2 * ng + 1], qfh[kq], kh4[1], kh4[3]);
            }
        }

        // mask + online softmax (base-2)
        const int kvalid = NTOT - kt * 64;
        if (kvalid < 64) {
#pragma unroll
            for (int nt = 0; nt < 8; nt++) {
                const int c0 = nt * 8 + 2 * tg;
                if (c0 >= kvalid)     { sacc[nt][0] = -1e30f; sacc[nt][2] = -1e30f; }
                if (c0 + 1 >= kvalid) { sacc[nt][1] = -1e30f; sacc[nt][3] = -1e30f; }
            }
        }
        float mx0 = -1e30f, mx1 = -1e30f;
#pragma unroll
        for (int nt = 0; nt < 8; nt++) {
            mx0 = fmaxf(mx0, fmaxf(sacc[nt][0], sacc[nt][1]));
            mx1 = fmaxf(mx1, fmaxf(sacc[nt][2], sacc[nt][3]));
        }
        mx0 = fmaxf(mx0, __shfl_xor_sync(0xffffffffu, mx0, 1));
        mx0 = fmaxf(mx0, __shfl_xor_sync(0xffffffffu, mx0, 2));
        mx1 = fmaxf(mx1, __shfl_xor_sync(0xffffffffu, mx1, 1));
        mx1 = fmaxf(mx1, __shfl_xor_sync(0xffffffffu, mx1, 2));
        const float mn0 = fmaxf(m0, mx0), mn1 = fmaxf(m1, mx1);
        const float cr0 = ex2f(m0 - mn0), cr1 = ex2f(m1 - mn1);
        m0 = mn0; m1 = mn1;
        float s0 = 0.f, s1 = 0.f;
#pragma unroll
        for (int nt = 0; nt < 8; nt++) {
            sacc[nt][0] = ex2f(sacc[nt][0] - mn0);
            sacc[nt][1] = ex2f(sacc[nt][1] - mn0);
            sacc[nt][2] = ex2f(sacc[nt][2] - mn1);
            sacc[nt][3] = ex2f(sacc[nt][3] - mn1);
            s0 += sacc[nt][0] + sacc[nt][1];
            s1 += sacc[nt][2] + sacc[nt][3];
        }
        s0 += __shfl_xor_sync(0xffffffffu, s0, 1);
        s0 += __shfl_xor_sync(0xffffffffu, s0, 2);
        s1 += __shfl_xor_sync(0xffffffffu, s1, 1);
        s1 += __shfl_xor_sync(0xffffffffu, s1, 2);
        l0 = l0 * cr0 + s0; l1 = l1 * cr1 + s1;
#pragma unroll
        for (int nt = 0; nt < 8; nt++) {
            oacc[nt][0] *= cr0; oacc[nt][1] *= cr0;
            oacc[nt][2] *= cr1; oacc[nt][3] *= cr1;
        }

        // O += P*V (V resident in the same buffer)
#pragma unroll
        for (int kc = 0; kc < 4; kc++) {
            uint32_t pah[4];
            const float* t0 = sacc[2 * kc];
            const float* t1 = sacc[2 * kc + 1];
            pah[0] = pkh(t0[0], t0[1]);
            pah[1] = pkh(t0[2], t0[3]);
            pah[2] = pkh(t1[0], t1[1]);
            pah[3] = pkh(t1[2], t1[3]);
            const int row = kc * 16 + l15;
#pragma unroll
            for (int ng = 0; ng < 4; ng++) {
                const int cc = 2 * ng + khalf;
                const uint32_t off = (row << 7) + ((cc ^ (row & 7)) << 4);
                uint32_t vh4[4];
                ldm4t(vh4, sVh + off);
                mma16816(oacc[2 * ng + 0], pah, vh4[0], vh4[1]);
                mma16816(oacc[2 * ng + 1], pah, vh4[2], vh4[3]);
            }
        }

        if (++bi == 3) bi = 0;
    }

    // normalize + write ctx as fp16 (out-proj A side)
    const float iv0 = 1.f / l0, iv1 = 1.f / l1;
    const int n0 = qt * 128 + w * 16 + g;
    const int n1 = n0 + 8;
#pragma unroll
    for (int nt = 0; nt < 8; nt++) {
        const int d = nt * 8 + 2 * tg;
        if (n0 < NTOT) {
            const long long idx = OFF_CTX + ((long long)(b * NTOT + n0)) * HIDDEN + h * HD + d;
            *(ushort2*)(g_bh + idx) = make_ushort2(h16(oacc[nt][0] * iv0),
                                                   h16(oacc[nt][1] * iv0));
        }
        if (n1 < NTOT) {
            const long long idx = OFF_CTX + ((long long)(b * NTOT + n1)) * HIDDEN + h * HD + d;
            *(ushort2*)(g_bh + idx) = make_ushort2(h16(oacc[nt][2] * iv1),
                                                   h16(oacc[nt][3] * iv1));
        }
    }
}

// ---------------- host launcher ----------------
extern "C" void kernel_launch(void* const* d_in, const int* in_sizes, int n_in,
                              void* d_out, int out_size)
{
    (void)out_size;
    const float* video = nullptr;
    const float* action = nullptr;
    const float* wb[16];
    int wi = 0;
    for (int i = 0; i < n_in; i++) {
        const int sz = in_sizes[i];
        if (sz == BSZ * NVID * HIDDEN)       video  = (const float*)d_in[i];
        else if (sz == BSZ * NACT * HIDDEN)  action = (const float*)d_in[i];
        else if (wi < 16)                    wb[wi++] = (const float*)d_in[i];
    }
    float* out = (float*)d_out;

    cudaFuncSetAttribute(gemm_qkv_mma, cudaFuncAttributeMaxDynamicSharedMemorySize, GT_SMEM);
    cudaFuncSetAttribute(gemm_out_mma, cudaFuncAttributeMaxDynamicSharedMemorySize, GO_SMEM);
    cudaFuncSetAttribute(attn_mma, cudaFuncAttributeMaxDynamicSharedMemorySize, AT_SMEM);

    // convert inputs + weights to fp16
    cvt_all<<<dim3(512, 10), 256>>>(video, action, wb[0], wb[2], wb[4], wb[6],
                                    wb[8], wb[10], wb[12], wb[14]);

    // QKV projections (rope + scale fused in epilogue)
    gemm_qkv_mma<<<dim3(8, 33, 3), 512, GT_SMEM>>>(wb[1], wb[3], wb[5],
                                                   wb[7], wb[9], wb[11]);

    // attention: 128-q-row CTAs, 64-key tiles, fused KV triple buffer, 2 CTAs/SM
    attn_mma<<<dim3(17, 32), 256, AT_SMEM>>>();

    // output projection: 128x64 tiles, 2 CTAs/SM
    gemm_out_mma<<<dim3(16, 17, 2), 256, GO_SMEM>>>(wb[13], wb[15], out);
}

// round 17
// speedup vs baseline: 1.0458x; 1.0458x over previous
#include <cuda_runtime.h>
#include <cuda_fp16.h>
#include <cstdint>

#define HIDDEN 1024
#define HEADS 16
#define HD 64
#define NVID 2048
#define NACT 16
#define NTOT 2064
#define BSZ 2
#define BH (BSZ*HEADS)
// q pre-scale: ATT_SCALE * log2(e), so softmax uses exp2
#define QSC 0.18033688011112042f

#define WSZ 1048576LL
#define OFF_VIDEO 0LL
#define OFF_ACTION 4194304LL
#define OFF_W 4227072LL
#define OFF_CTX (OFF_W + 8LL * WSZ)
#define BF_TOTAL (OFF_CTX + 4227072LL)

// ---------------- scratch (device globals; no allocation allowed) ----------------
__device__ unsigned short g_bh[BF_TOTAL];    // fp16: inputs, weights, ctx
__device__ unsigned short g_qh[BH * NTOT * HD];
__device__ unsigned short g_kh[BH * NTOT * HD];
__device__ unsigned short g_vh[BH * NTOT * HD];

// ---------------- helpers ----------------
__device__ __forceinline__ void cpa16z(uint32_t dst, const void* src, int bytes) {
    asm volatile("cp.async.cg.shared.global [%0], [%1], 16, %2;"
                 :: "r"(dst), "l"(src), "r"(bytes) : "memory");
}
__device__ __forceinline__ void cp_commit() {
    asm volatile("cp.async.commit_group;" ::: "memory");
}
__device__ __forceinline__ uint32_t smem_u32(const void* p) {
    return (uint32_t)__cvta_generic_to_shared(p);
}
__device__ __forceinline__ void ldm4(uint32_t* r, uint32_t addr) {
    asm volatile("ldmatrix.sync.aligned.m8n8.x4.shared.b16 {%0,%1,%2,%3}, [%4];"
                 : "=r"(r[0]), "=r"(r[1]), "=r"(r[2]), "=r"(r[3]) : "r"(addr));
}
__device__ __forceinline__ void ldm4t(uint32_t* r, uint32_t addr) {
    asm volatile("ldmatrix.sync.aligned.m8n8.x4.trans.shared.b16 {%0,%1,%2,%3}, [%4];"
                 : "=r"(r[0]), "=r"(r[1]), "=r"(r[2]), "=r"(r[3]) : "r"(addr));
}
__device__ __forceinline__ void mma16816(float* c, const uint32_t* a,
                                         uint32_t b0, uint32_t b1) {
    asm volatile("mma.sync.aligned.m16n8k16.row.col.f32.f16.f16.f32 "
                 "{%0,%1,%2,%3}, {%4,%5,%6,%7}, {%8,%9}, {%0,%1,%2,%3};"
                 : "+f"(c[0]), "+f"(c[1]), "+f"(c[2]), "+f"(c[3])
                 : "r"(a[0]), "r"(a[1]), "r"(a[2]), "r"(a[3]), "r"(b0), "r"(b1));
}
__device__ __forceinline__ unsigned short h16(float x) {
    return __half_as_ushort(__float2half_rn(x));
}
__device__ __forceinline__ uint32_t pkh(float lo, float hi) {
    uint32_t r;
    asm("cvt.rn.f16x2.f32 %0, %1, %2;" : "=r"(r) : "f"(hi), "f"(lo));
    return r;
}
__device__ __forceinline__ float ex2f(float x) {
    float y; asm("ex2.approx.ftz.f32 %0, %1;" : "=f"(y) : "f"(x)); return y;
}

// ---------------- fp32 -> fp16 convert (inputs + weights), 16B stores ----------------
__global__ void cvt_all(const float* v, const float* a,
                        const float* w0, const float* w1, const float* w2,
                        const float* w3, const float* w4, const float* w5,
                        const float* w6, const float* w7)
{
    const float* srcs[10] = { v, a, w0, w1, w2, w3, w4, w5, w6, w7 };
    const long long offs[10] = { OFF_VIDEO, OFF_ACTION,
        OFF_W + 0 * WSZ, OFF_W + 1 * WSZ, OFF_W + 2 * WSZ, OFF_W + 3 * WSZ,
        OFF_W + 4 * WSZ, OFF_W + 5 * WSZ, OFF_W + 6 * WSZ, OFF_W + 7 * WSZ };
    const int cnts[10] = { 4194304, 32768, 1048576, 1048576, 1048576, 1048576,
                           1048576, 1048576, 1048576, 1048576 };
    const int z = blockIdx.y;
    const float4* src = (const float4*)srcs[z];
    uint4* dst = (uint4*)(g_bh + offs[z]);
    const int n8 = cnts[z] >> 3;
    for (int i = blockIdx.x * blockDim.x + threadIdx.x; i < n8;
         i += gridDim.x * blockDim.x) {
        const float4 x = src[2 * i];
        const float4 y = src[2 * i + 1];
        uint4 o;
        o.x = pkh(x.x, x.y);
        o.y = pkh(x.z, x.w);
        o.z = pkh(y.x, y.y);
        o.w = pkh(y.z, y.w);
        dst[i] = o;
    }
}

// ================= qkv GEMM: 128x128 tile, 512 threads (at HMMA ceiling) =========
#define GT_TILE 16384
#define GT_BUF  (2 * GT_TILE)
#define GT_SMEM (2 * GT_BUF)          // 64 KB

__device__ __forceinline__ void gstage(const unsigned short* Ah,
                                       int M, int rowTile,
                                       const unsigned short* Wh,
                                       int colTile, int k0, uint32_t bufb, int tid)
{
#pragma unroll
    for (int i = 0; i < 4; i++) {
        const int tile = i >> 1;
        const int t = ((i & 1) << 9) + tid;
        const int row = t >> 3, c = t & 7;
        const uint32_t dst = bufb + tile * GT_TILE + (row << 7) + ((c ^ (row & 7)) << 4);
        if (tile == 0) {
            const int m = rowTile + row;
            const int mm = (m < M) ? m : 0;
            cpa16z(dst, Ah + (long long)mm * 1024 + k0 + c * 8, (m < M) ? 16 : 0);
        } else {
            cpa16z(dst, Wh + (long long)(colTile + row) * 1024 + k0 + c * 8, 16);
        }
    }
}

// MODE 1: video qkv + rope;  MODE 2: action qkv
template <int MODE>
__device__ __forceinline__ void gemm_body(const unsigned short* Ah,
                                          int M, int rowTile,
                                          const unsigned short* Wh,
                                          int colTile, const float* bias,
                                          unsigned short* __restrict__ oh, int rk)
{
    extern __shared__ char dsmem[];
    const uint32_t sbase = smem_u32(dsmem);
    const int tid = threadIdx.x;
    const int lane = tid & 31, wid = tid >> 5;
    const int warp_m = wid >> 2, warp_n = wid & 3;

    float acc[2][4][4];
#pragma unroll
    for (int a = 0; a < 2; a++)
#pragma unroll
        for (int b = 0; b < 4; b++)
#pragma unroll
            for (int c = 0; c < 4; c++) acc[a][b][c] = 0.f;

    int rA[2], rW[2];
#pragma unroll
    for (int mt = 0; mt < 2; mt++) rA[mt] = warp_m * 32 + mt * 16 + (lane & 15);
#pragma unroll
    for (int nt2 = 0; nt2 < 2; nt2++) rW[nt2] = warp_n * 32 + nt2 * 16 + (lane & 15);
    const int khalf = lane >> 4;

    gstage(Ah, M, rowTile, Wh, colTile, 0, sbase, tid);
    cp_commit();

    for (int c = 0; c < 16; c++) {
        if (c + 1 < 16) {
            gstage(Ah, M, rowTile, Wh, colTile, (c + 1) * 64,
                   sbase + ((c + 1) & 1) * GT_BUF, tid);
            cp_commit();
            asm volatile("cp.async.wait_group 1;" ::: "memory");
        } else {
            asm volatile("cp.async.wait_group 0;" ::: "memory");
        }
        __syncthreads();

        const uint32_t bufb = sbase + (c & 1) * GT_BUF;
        const uint32_t sAh = bufb;
        const uint32_t sWh = bufb + GT_TILE;

#pragma unroll
        for (int kq = 0; kq < 4; kq++) {
            const int kp = 2 * kq + khalf;
            uint32_t ah[2][4], wh[2][4];
#pragma unroll
            for (int mt = 0; mt < 2; mt++) {
                const uint32_t off = (rA[mt] << 7) + ((kp ^ (rA[mt] & 7)) << 4);
                ldm4(ah[mt], sAh + off);
            }
#pragma unroll
            for (int nt2 = 0; nt2 < 2; nt2++) {
                const uint32_t off = (rW[nt2] << 7) + ((kp ^ (rW[nt2] & 7)) << 4);
                ldm4(wh[nt2], sWh + off);
            }
#pragma unroll
            for (int mt = 0; mt < 2; mt++) {
#pragma unroll
                for (int nt = 0; nt < 4; nt++) {
                    const uint32_t* whf = wh[nt >> 1];
                    mma16816(acc[mt][nt], ah[mt], whf[nt & 1], whf[(nt & 1) + 2]);
                }
            }
        }
        __syncthreads();
    }

    const int g = lane >> 2, tg = lane & 3;
#pragma unroll
    for (int mt = 0; mt < 2; mt++) {
#pragma unroll
        for (int nt = 0; nt < 4; nt++) {
            const int n0 = colTile + warp_n * 32 + nt * 8 + tg * 2;
            const float2 bv = *(const float2*)(bias + n0);
#pragma unroll
            for (int hf = 0; hf < 2; hf++) {
                const int m = rowTile + warp_m * 32 + mt * 16 + g + hf * 8;
                if (m >= M) continue;
                float v0 = acc[mt][nt][hf * 2 + 0] + bv.x;
                float v1 = acc[mt][nt][hf * 2 + 1] + bv.y;
                int b_, nn;
                if (MODE == 1) { b_ = m >> 11; nn = m & 2047; }
                else           { b_ = m >> 4;  nn = NVID + (m & 15); }
                const int hh = n0 >> 6, d = n0 & 63;
                if (MODE == 1 && rk && d < 60) {
                    const int seg = d / 20, jj = (d - seg * 20) >> 1;
                    const int pos = (seg == 0) ? (nn >> 8)
                                  : (seg == 1) ? ((nn >> 4) & 15) : (nn & 15);
                    const float omega = ex2f(-(float)jj * 1.3287712379549449f);
                    float sn, cs;
                    sincosf((float)pos * omega, &sn, &cs);
                    const float x1 = v0 * cs - v1 * sn;
                    const float x2 = v1 * cs + v0 * sn;
                    v0 = x1; v1 = x2;
                }
                if (rk == 1) { v0 *= QSC; v1 *= QSC; }
                const long long idx = (((long long)(b_ * HEADS + hh)) * NTOT + nn) * HD + d;
                *(ushort2*)(oh + idx) = make_ushort2(h16(v0), h16(v1));
            }
        }
    }
}

// grid (8, 33, 3): z = {q,k,v}; by<32 video rows; by==32 action rows
__global__ __launch_bounds__(512, 1)
void gemm_qkv_mma(const float* bq, const float* bk, const float* bv,
                  const float* bqa, const float* bka, const float* bva)
{
    const int z = blockIdx.z;
    const bool act = (blockIdx.y == 32);
    const unsigned short* Ah = g_bh + (act ? OFF_ACTION : OFF_VIDEO);
    const int M = act ? (BSZ * NACT) : (BSZ * NVID);
    const int rowTile = act ? 0 : blockIdx.y * 128;
    const int colTile = blockIdx.x * 128;
    const int widx = z + (act ? 3 : 0);
    const unsigned short* Wh = g_bh + OFF_W + widx * WSZ;
    const float* bias = act ? (z == 0 ? bqa : (z == 1 ? bka : bva))
                            : (z == 0 ? bq : (z == 1 ? bk : bv));
    unsigned short* oh;
    int rk;
    if (z == 0)      { oh = g_qh; rk = 1; }
    else if (z == 1) { oh = g_kh; rk = 2; }
    else             { oh = g_vh; rk = 0; }
    if (act) gemm_body<2>(Ah, M, rowTile, Wh, colTile, bias, oh, rk);
    else     gemm_body<1>(Ah, M, rowTile, Wh, colTile, bias, oh, rk);
}

// ================= out GEMM: 128x64 tile, 256 threads, 2 CTAs/SM =================
#define GO_ATILE 16384                 // 128 rows * 128 B
#define GO_WTILE 8192                  // 64 rows * 128 B
#define GO_BUF   (GO_ATILE + GO_WTILE) // 24 KB
#define GO_SMEM  (2 * GO_BUF)          // 48 KB

__device__ __forceinline__ void gstage_o(const unsigned short* Ah,
                                         int M, int rowTile,
                                         const unsigned short* Wh,
                                         int colTile, int k0, uint32_t bufb, int tid)
{
#pragma unroll
    for (int i = 0; i < 6; i++) {
        if (i < 4) {       // A tile: 1024 chunks
            const int t = (i << 8) + tid;
            const int row = t >> 3, c = t & 7;
            const uint32_t dst = bufb + (row << 7) + ((c ^ (row & 7)) << 4);
            const int m = rowTile + row;
            const int mm = (m < M) ? m : 0;
            cpa16z(dst, Ah + (long long)mm * 1024 + k0 + c * 8, (m < M) ? 16 : 0);
        } else {           // W tile: 512 chunks
            const int t = ((i - 4) << 8) + tid;
            const int row = t >> 3, c = t & 7;
            const uint32_t dst = bufb + GO_ATILE + (row << 7) + ((c ^ (row & 7)) << 4);
            cpa16z(dst, Wh + (long long)(colTile + row) * 1024 + k0 + c * 8, 16);
        }
    }
}

// grid (16, 17, 2): z = batch; by<16 video rows; by==16 action rows
__global__ __launch_bounds__(256, 2)
void gemm_out_mma(const float* bp, const float* bpa, float* __restrict__ dout)
{
    extern __shared__ char dsmem[];
    const uint32_t sbase = smem_u32(dsmem);
    const int z = blockIdx.z;
    const bool act = (blockIdx.y == 16);
    const long long aoff = OFF_CTX + (long long)z * NTOT * HIDDEN +
                           (act ? (long long)NVID * HIDDEN : 0);
    const unsigned short* Ah = g_bh + aoff;
    const int M = act ? NACT : NVID;
    const int rowTile = act ? 0 : blockIdx.y * 128;
    const int colTile = blockIdx.x * 64;
    const int widx = act ? 7 : 6;
    const unsigned short* Wh = g_bh + OFF_W + widx * WSZ;
    const float* bias = act ? bpa : bp;
    float* C = act ? (dout + (long long)BSZ * NVID * HIDDEN + (long long)z * NACT * HIDDEN)
                   : (dout + (long long)z * NVID * HIDDEN);

    const int tid = threadIdx.x;
    const int lane = tid & 31, wid = tid >> 5;
    const int warp_m = wid >> 1, warp_n = wid & 1;   // 4 x 2 warps

    float acc[2][4][4];
#pragma unroll
    for (int a = 0; a < 2; a++)
#pragma unroll
        for (int b = 0; b < 4; b++)
#pragma unroll
            for (int c = 0; c < 4; c++) acc[a][b][c] = 0.f;

    int rA[2], rW[2];
#pragma unroll
    for (int mt = 0; mt < 2; mt++) rA[mt] = warp_m * 32 + mt * 16 + (lane & 15);
#pragma unroll
    for (int nt2 = 0; nt2 < 2; nt2++) rW[nt2] = warp_n * 32 + nt2 * 16 + (lane & 15);
    const int khalf = lane >> 4;

    gstage_o(Ah, M, rowTile, Wh, colTile, 0, sbase, tid);
    cp_commit();

    for (int c = 0; c < 16; c++) {
        if (c + 1 < 16) {
            gstage_o(Ah, M, rowTile, Wh, colTile, (c + 1) * 64,
                     sbase + ((c + 1) & 1) * GO_BUF, tid);
            cp_commit();
            asm volatile("cp.async.wait_group 1;" ::: "memory");
        } else {
            asm volatile("cp.async.wait_group 0;" ::: "memory");
        }
        __syncthreads();

        const uint32_t bufb = sbase + (c & 1) * GO_BUF;
        const uint32_t sAh = bufb;
        const uint32_t sWh = bufb + GO_ATILE;

#pragma unroll
        for (int kq = 0; kq < 4; kq++) {
            const int kp = 2 * kq + khalf;
            uint32_t ah[2][4], wh[2][4];
#pragma unroll
            for (int mt = 0; mt < 2; mt++) {
                const uint32_t off = (rA[mt] << 7) + ((kp ^ (rA[mt] & 7)) << 4);
                ldm4(ah[mt], sAh + off);
            }
#pragma unroll
            for (int nt2 = 0; nt2 < 2; nt2++) {
                const uint32_t off = (rW[nt2] << 7) + ((kp ^ (rW[nt2] & 7)) << 4);
                ldm4(wh[nt2], sWh + off);
            }
#pragma unroll
            for (int mt = 0; mt < 2; mt++) {
#pragma unroll
                for (int nt = 0; nt < 4; nt++) {
                    const uint32_t* whf = wh[nt >> 1];
                    mma16816(acc[mt][nt], ah[mt], whf[nt & 1], whf[(nt & 1) + 2]);
                }
            }
        }
        __syncthreads();
    }

    const int g = lane >> 2, tg = lane & 3;
#pragma unroll
    for (int mt = 0; mt < 2; mt++) {
#pragma unroll
        for (int nt = 0; nt < 4; nt++) {
            const int n0 = colTile + warp_n * 32 + nt * 8 + tg * 2;
            const float2 bv = *(const float2*)(bias + n0);
#pragma unroll
            for (int hf = 0; hf < 2; hf++) {
                const int m = rowTile + warp_m * 32 + mt * 16 + g + hf * 8;
                if (m >= M) continue;
                float2 o;
                o.x = acc[mt][nt][hf * 2 + 0] + bv.x;
                o.y = acc[mt][nt][hf * 2 + 1] + bv.y;
                *(float2*)(C + (long long)m * 1024 + n0) = o;
            }
        }
    }
}

// ================= flash attention: 64 q-rows, 4 warps, 4 CTAs/SM ==============
// Q held in registers (loaded directly from global; no Q smem / staging).
// Triple-buffered fused K+V tiles (16 KB each: K at +0, V at +8K).
// One wait_group(1) + one __syncthreads per key tile; prefetch distance 2.
#define AT_BUF(i) ((i) * 16384)
#define AT_SMEM (3 * 16384)           // 49152 -> 4 CTAs/SM

__device__ __forceinline__ void stage_kv64(long long base, int kt, uint32_t bufb, int tid) {
#pragma unroll
    for (int i = 0; i < 8; i++) {
        const int arr = i >> 2;                  // 0 = K, 1 = V
        const int t = ((i & 3) << 7) + tid;      // 0..511
        const int row = t >> 3, c = t & 7;
        const int key = kt * 64 + row;
        const uint32_t dst = bufb + arr * 8192 + (row << 7) + ((c ^ (row & 7)) << 4);
        const unsigned short* s = (arr == 0 ? g_kh : g_vh) +
            base + (long long)(key < NTOT ? key : 0) * HD + c * 8;
        cpa16z(dst, s, (key < NTOT) ? 16 : 0);
    }
}

__global__ __launch_bounds__(128, 4)
void attn_mma()
{
    extern __shared__ char dsm[];
    const uint32_t sb = smem_u32(dsm);
    const int tid = threadIdx.x, lane = tid & 31, w = tid >> 5;
    const int qt = blockIdx.x, bh = blockIdx.y;
    const int b = bh >> 4, h = bh & 15;
    const long long base = (long long)bh * NTOT * HD;
    const int g = lane >> 2, tg = lane & 3;
    const int khalf = lane >> 4, l15 = lane & 15;

    // prologue: KV0, KV1 via cp.async (two groups)
    stage_kv64(base, 0, sb + AT_BUF(0), tid);
    cp_commit();
    stage_kv64(base, 1, sb + AT_BUF(1), tid);
    cp_commit();

    // Q fragments loaded directly from global (mma A-operand layout):
    // qfh[kq][0]=(row g, k 2tg), [1]=(row g+8), [2]=(row g, k 8+2tg), [3]=(row g+8)
    uint32_t qfh[4][4];
    {
        const int r0 = qt * 64 + w * 16 + g;
        const int r1 = r0 + 8;
        const unsigned short* q0 = g_qh + base + (long long)(r0 < NTOT ? r0 : 0) * HD;
        const unsigned short* q1 = g_qh + base + (long long)(r1 < NTOT ? r1 : 0) * HD;
#pragma unroll
        for (int kq = 0; kq < 4; kq++) {
            const int kb = kq * 16 + 2 * tg;
            qfh[kq][0] = *(const uint32_t*)(q0 + kb);
            qfh[kq][1] = *(const uint32_t*)(q1 + kb);
            qfh[kq][2] = *(const uint32_t*)(q0 + kb + 8);
            qfh[kq][3] = *(const uint32_t*)(q1 + kb + 8);
        }
    }

    float oacc[8][4];
#pragma unroll
    for (int i = 0; i < 8; i++)
#pragma unroll
        for (int j = 0; j < 4; j++) oacc[i][j] = 0.f;
    float m0 = -1e30f, m1 = -1e30f, l0 = 0.f, l1 = 0.f;

    const int NKT = 33;   // 33 * 64 = 2112 >= 2064
    int bi = 0;           // kt % 3
    for (int kt = 0; kt < NKT; kt++) {
        // ensure KV(kt) landed (KV(kt+1) may still be in flight)
        asm volatile("cp.async.wait_group 1;" ::: "memory");
        __syncthreads();

        // prefetch KV(kt+2) into the buffer consumed at iteration kt-1
        if (kt + 2 < NKT) {
            int nb = bi + 2; if (nb >= 3) nb -= 3;
            stage_kv64(base, kt + 2, sb + AT_BUF(nb), tid);
        }
        cp_commit();   // always commit to keep group accounting aligned

        const uint32_t sKh = sb + AT_BUF(bi);
        const uint32_t sVh = sKh + 8192;

        float sacc[8][4];
#pragma unroll
        for (int i = 0; i < 8; i++)
#pragma unroll
            for (int j = 0; j < 4; j++) sacc[i][j] = 0.f;

        // S = Q*K, 64 keys
#pragma unroll
        for (int kq = 0; kq < 4; kq++) {
            const int kp = 2 * kq + khalf;
#pragma unroll
            for (int ng = 0; ng < 4; ng++) {
                const int row = ng * 16 + l15;
                const uint32_t off = (row << 7) + ((kp ^ (row & 7)) << 4);
                uint32_t kh4[4];
                ldm4(kh4, sKh + off);
                mma16816(sacc[2 * ng + 0], qfh[kq], kh4[0], kh4[2]);
                mma16816(sacc[2 * ng + 1], qfh[kq], kh4[1], kh4[3]);
            }
        }

        // mask + online softmax (base-2)
        const int kvalid = NTOT - kt * 64;
        if (kvalid < 64) {
#pragma unroll
            for (int nt = 0; nt < 8; nt++) {
                const int c0 = nt * 8 + 2 * tg;
                if (c0 >= kvalid)     { sacc[nt][0] = -1e30f; sacc[nt][2] = -1e30f; }
                if (c0 + 1 >= kvalid) { sacc[nt][1] = -1e30f; sacc[nt][3] = -1e30f; }
            }
        }
        float mx0 = -1e30f, mx1 = -1e30f;
#pragma unroll
        for (int nt = 0; nt < 8; nt++) {
            mx0 = fmaxf(mx0, fmaxf(sacc[nt][0], sacc[nt][1]));
            mx1 = fmaxf(mx1, fmaxf(sacc[nt][2], sacc[nt][3]));
        }
        mx0 = fmaxf(mx0, __shfl_xor_sync(0xffffffffu, mx0, 1));
        mx0 = fmaxf(mx0, __shfl_xor_sync(0xffffffffu, mx0, 2));
        mx1 = fmaxf(mx1, __shfl_xor_sync(0xffffffffu, mx1, 1));
        mx1 = fmaxf(mx1, __shfl_xor_sync(0xffffffffu, mx1, 2));
        const float mn0 = fmaxf(m0, mx0), mn1 = fmaxf(m1, mx1);
        const float cr0 = ex2f(m0 - mn0), cr1 = ex2f(m1 - mn1);
        m0 = mn0; m1 = mn1;
        float s0 = 0.f, s1 = 0.f;
#pragma unroll
        for (int nt = 0; nt < 8; nt++) {
            sacc[nt][0] = ex2f(sacc[nt][0] - mn0);
            sacc[nt][1] = ex2f(sacc[nt][1] - mn0);
            sacc[nt][2] = ex2f(sacc[nt][2] - mn1);
            sacc[nt][3] = ex2f(sacc[nt][3] - mn1);
            s0 += sacc[nt][0] + sacc[nt][1];
            s1 += sacc[nt][2] + sacc[nt][3];
        }
        s0 += __shfl_xor_sync(0xffffffffu, s0, 1);
        s0 += __shfl_xor_sync(0xffffffffu, s0, 2);
        s1 += __shfl_xor_sync(0xffffffffu, s1, 1);
        s1 += __shfl_xor_sync(0xffffffffu, s1, 2);
        l0 = l0 * cr0 + s0; l1 = l1 * cr1 + s1;
#pragma unroll
        for (int nt = 0; nt < 8; nt++) {
            oacc[nt][0] *= cr0; oacc[nt][1] *= cr0;
            oacc[nt][2] *= cr1; oacc[nt][3] *= cr1;
        }

        // O += P*V (V already resident in the same buffer)
#pragma unroll
        for (int kc = 0; kc < 4; kc++) {
            uint32_t pah[4];
            const float* t0 = sacc[2 * kc];
            const float* t1 = sacc[2 * kc + 1];
            pah[0] = pkh(t0[0], t0[1]);
            pah[1] = pkh(t0[2], t0[3]);
            pah[2] = pkh(t1[0], t1[1]);
            pah[3] = pkh(t1[2], t1[3]);
            const int row = kc * 16 + l15;
#pragma unroll
            for (int ng = 0; ng < 4; ng++) {
                const int cc = 2 * ng + khalf;
                const uint32_t off = (row << 7) + ((cc ^ (row & 7)) << 4);
                uint32_t vh4[4];
                ldm4t(vh4, sVh + off);
                mma16816(oacc[2 * ng + 0], pah, vh4[0], vh4[1]);
                mma16816(oacc[2 * ng + 1], pah, vh4[2], vh4[3]);
            }
        }

        if (++bi == 3) bi = 0;
    }

    // normalize + write ctx as fp16 (out-proj A side)
    const float iv0 = 1.f / l0, iv1 = 1.f / l1;
    const int n0 = qt * 64 + w * 16 + g;
    const int n1 = n0 + 8;
#pragma unroll
    for (int nt = 0; nt < 8; nt++) {
        const int d = nt * 8 + 2 * tg;
        if (n0 < NTOT) {
            const long long idx = OFF_CTX + ((long long)(b * NTOT + n0)) * HIDDEN + h * HD + d;
            *(ushort2*)(g_bh + idx) = make_ushort2(h16(oacc[nt][0] * iv0),
                                                   h16(oacc[nt][1] * iv0));
        }
        if (n1 < NTOT) {
            const long long idx = OFF_CTX + ((long long)(b * NTOT + n1)) * HIDDEN + h * HD + d;
            *(ushort2*)(g_bh + idx) = make_ushort2(h16(oacc[nt][2] * iv1),
                                                   h16(oacc[nt][3] * iv1));
        }
    }
}

// ---------------- host launcher ----------------
extern "C" void kernel_launch(void* const* d_in, const int* in_sizes, int n_in,
                              void* d_out, int out_size)
{
    (void)out_size;
    const float* video = nullptr;
    const float* action = nullptr;
    const float* wb[16];
    int wi = 0;
    for (int i = 0; i < n_in; i++) {
        const int sz = in_sizes[i];
        if (sz == BSZ * NVID * HIDDEN)       video  = (const float*)d_in[i];
        else if (sz == BSZ * NACT * HIDDEN)  action = (const float*)d_in[i];
        else if (wi < 16)                    wb[wi++] = (const float*)d_in[i];
    }
    float* out = (float*)d_out;

    cudaFuncSetAttribute(gemm_qkv_mma, cudaFuncAttributeMaxDynamicSharedMemorySize, GT_SMEM);
    cudaFuncSetAttribute(gemm_out_mma, cudaFuncAttributeMaxDynamicSharedMemorySize, GO_SMEM);
    cudaFuncSetAttribute(attn_mma, cudaFuncAttributeMaxDynamicSharedMemorySize, AT_SMEM);

    // convert inputs + weights to fp16
    cvt_all<<<dim3(512, 10), 256>>>(video, action, wb[0], wb[2], wb[4], wb[6],
                                    wb[8], wb[10], wb[12], wb[14]);

    // QKV projections (rope + scale fused in epilogue)
    gemm_qkv_mma<<<dim3(8, 33, 3), 512, GT_SMEM>>>(wb[1], wb[3], wb[5],
                                                   wb[7], wb[9], wb[11]);

    // attention: 64-q-row CTAs, 64-key tiles, Q in registers, 4 CTAs/SM
    attn_mma<<<dim3(33, 32), 128, AT_SMEM>>>();

    // output projection: 128x64 tiles, 2 CTAs/SM
    gemm_out_mma<<<dim3(16, 17, 2), 256, GO_SMEM>>>(wb[13], wb[15], out);
}